// round 15
// baseline (speedup 1.0000x reference)
#include <cuda_runtime.h>

#define B 8
#define M 2048
#define N 2048
#define IN 256
#define TM 8
#define TN 1024
#define NCHUNK 8
#define DCHUNK 16   // 128 / NCHUNK
#define NFOLD 16    // fold blocks = NCHUNK * 2

// ---- scratch (allocation-free: __device__ globals) ----
__device__ int   g_ctr;                 // fold-completion counter (reset by fused)
__device__ float g_vp[2][NCHUNK][IN];   // partial folds of W^T @ Wc half
__device__ float g_consts[2];
__device__ float g_s0[B * M];       // s0 + const0
__device__ float g_ls0[B * M];      // logsig(z0)
__device__ float g_lsn0[B * M];     // logsig(-z0)
__device__ float g_s1b[B * N];      // s1 + const1 (bc folded)
__device__ float g_ls1[B * N];      // logsig(z1)
__device__ float g_lsn1[B * N];     // logsig(-z1)

// Negated coefficients of deg-6 poly for ln(1+u), u in [0,1]
#define PC0 (-1.79e-6f)
#define PC1 (-0.99984773f)
#define PC2 ( 0.49737292f)
#define PC3 (-0.31574592f)
#define PC4 ( 0.19035072f)
#define PC5 (-0.08269517f)
#define PC6 ( 0.01741517f)
#define NEG_L2E (-1.4426950408889634f)

__device__ __forceinline__ float ex2_(float x) {
    float r; asm("ex2.approx.f32 %0, %1;" : "=f"(r) : "f"(x)); return r;
}

// streaming (evict-first) stores: output is written once, never re-read
__device__ __forceinline__ void stg_cs4(float* p, float4 v) {
    asm volatile("st.global.cs.v4.f32 [%0], {%1, %2, %3, %4};"
                 :: "l"(p), "f"(v.x), "f"(v.y), "f"(v.z), "f"(v.w) : "memory");
}
__device__ __forceinline__ void stg_cs(float* p, float v) {
    asm volatile("st.global.cs.f32 [%0], %1;" :: "l"(p), "f"(v) : "memory");
}
__device__ __forceinline__ int ld_acq(const int* p) {
    int v; asm volatile("ld.acquire.gpu.global.s32 %0, [%1];" : "=r"(v) : "l"(p) : "memory");
    return v;
}

__device__ __forceinline__ float lsig(float x) {   // reference-accurate, tiny arrays only
    return fminf(x, 0.0f) - __logf(1.0f + __expf(-fabsf(x)));
}

// fast scalar log-sigmoid + q:  min(c,0) - log1p(exp(-|c|)) + q
__device__ __forceinline__ float lsig_fast(float c, float q) {
    float u = ex2_(fabsf(c) * NEG_L2E);          // exp(-|c|), 1 MUFU
    float p = fmaf(PC6, u, PC5);
    p = fmaf(p, u, PC4);
    p = fmaf(p, u, PC3);
    p = fmaf(p, u, PC2);
    p = fmaf(p, u, PC1);
    p = fmaf(p, u, PC0);                         // p = -log1p(u)
    return fminf(c, 0.0f) + p + q;
}

// ---- kernel 1: fold + per-row dot products (single kernel, flag protocol) ----
// 1D grid of 4096 blocks: bid&1 = which, bid>>1 = row block (8 warps = 8 rows).
// Bids 0..15 are dispatched first (wave-1 resident) and each fold one
// (chunk, which) slice of W^T*Wc into g_vp, then release g_ctr. All blocks
// issue desc loads BEFORE spinning, so the fold hides under the DRAM stream.
__global__ void __launch_bounds__(256) rows_kernel(
    const float* __restrict__ d0, const float* __restrict__ d1,
    const float* __restrict__ W0, const float* __restrict__ b0v,
    const float* __restrict__ W1, const float* __restrict__ b1v,
    const float* __restrict__ Wm, const float* __restrict__ bm,
    const float* __restrict__ Wc, const float* __restrict__ bc) {
    int bid   = blockIdx.x;
    int which = bid & 1;
    int rowblk = bid >> 1;
    const float* desc = which ? d1 : d0;
    int tx = threadIdx.x, warp = tx >> 5, lane = tx & 31;
    int row = rowblk * 8 + warp;
    int k0 = lane, k1 = lane + 32;

    // issue desc row + Wm loads first (independent of fold)
    const float4* dp = (const float4*)(desc + (size_t)row * IN);
    float4 a0 = dp[k0];
    float4 a1 = dp[k1];
    float4 wv0 = ((const float4*)Wm)[k0];
    float4 wv1 = ((const float4*)Wm)[k1];
    float bmv = bm[0];
    float az = a0.x * wv0.x + a0.y * wv0.y + a0.z * wv0.z + a0.w * wv0.w
             + a1.x * wv1.x + a1.y * wv1.y + a1.z * wv1.z + a1.w * wv1.w;

    // fold producers: first NFOLD bids
    if (bid < NFOLD) {
        int chunk = bid >> 1;             // 0..NCHUNK-1 (which = bid&1)
        const float* W  = which ? W1 : W0;
        const float* wc = Wc + which * 128;
        float a = 0.f;
        int dbase = chunk * DCHUNK;
        #pragma unroll
        for (int dd = 0; dd < DCHUNK; dd++) {
            int d = dbase + dd;
            a += W[d * IN + tx] * wc[d];
        }
        g_vp[which][chunk][tx] = a;
        if (chunk == 0 && tx < 32) {      // bias consts (bids 0 and 1)
            const float* bias = which ? b1v : b0v;
            float c = 0.f;
            #pragma unroll
            for (int d = tx; d < 128; d += 32) c += bias[d] * wc[d];
            #pragma unroll
            for (int o = 16; o; o >>= 1) c += __shfl_down_sync(0xffffffffu, c, o);
            if (tx == 0) g_consts[which] = which ? (c + bc[0]) : c;
        }
        __threadfence();                  // make this thread's stores visible
        __syncthreads();                  // all threads fenced
        if (tx == 0) atomicAdd(&g_ctr, 1);
    }

    // consumers: spin until all NFOLD partials published
    if (tx == 0) {
        while (ld_acq(&g_ctr) < NFOLD) { }
    }
    __syncthreads();

    // reduce partials into smem (L2-only loads: dodge non-coherent L1)
    __shared__ float sh_v[IN];
    {
        float a = 0.f;
        #pragma unroll
        for (int c = 0; c < NCHUNK; c++) a += __ldcg(&g_vp[which][c][tx]);
        sh_v[tx] = a;
    }
    __syncthreads();

    float4 vv0 = ((const float4*)sh_v)[k0];
    float4 vv1 = ((const float4*)sh_v)[k1];
    float as = a0.x * vv0.x + a0.y * vv0.y + a0.z * vv0.z + a0.w * vv0.w
             + a1.x * vv1.x + a1.y * vv1.y + a1.z * vv1.z + a1.w * vv1.w;

    #pragma unroll
    for (int o = 16; o; o >>= 1) {
        as += __shfl_down_sync(0xffffffffu, as, o);
        az += __shfl_down_sync(0xffffffffu, az, o);
    }
    if (lane == 0) {
        float z = az + bmv;
        float cst = __ldcg(&g_consts[which]);
        if (which == 0) {
            g_s0[row]   = as + cst;
            g_ls0[row]  = lsig(z);
            g_lsn0[row] = lsig(-z);
        } else {
            g_s1b[row]  = as + cst;
            g_ls1[row]  = lsig(z);
            g_lsn1[row] = lsig(-z);
        }
    }
}

// ---- fused tile body, templated on SB = b & 3 ----
// probs row (b,m) starts at global offset ≡ (b+m) mod 4; per-row shift
// s = (-(b+r)) & 3 makes stores at col s+4t 16B-aligned. Thread t holds an
// 8-value s1/ls1 register window (cols 4t..4t+7); threads 0/255 mop up
// <=4 boundary scalars per row. All stores use evict-first (.cs) hints.
template<int SB>
__device__ __forceinline__ void tile_body(
    float* __restrict__ prow0, float4* __restrict__ crow,
    const float* sh_s0, const float* sh_ls0,
    const float* s1w, const float* lw, int tx, bool wc)
{
    #pragma unroll
    for (int r = 0; r < TM; r++) {
        const int s = (16 - SB - r) & 3;   // alignment shift: (b+r+s) % 4 == 0
        float s0 = sh_s0[r];
        float l0 = sh_ls0[r];

        if (wc) {
            stg_cs4((float*)crow,
                    make_float4(s0 + s1w[0], s0 + s1w[1], s0 + s1w[2], s0 + s1w[3]));
            crow += N / 4;
        }

        float v0 = lsig_fast(s0 + s1w[s + 0], l0 + lw[s + 0]);
        float v1 = lsig_fast(s0 + s1w[s + 1], l0 + lw[s + 1]);
        float v2 = lsig_fast(s0 + s1w[s + 2], l0 + lw[s + 2]);
        float v3 = lsig_fast(s0 + s1w[s + 3], l0 + lw[s + 3]);

        float* prow = prow0 + (size_t)r * (N + 1);
        if (s == 0) {
            stg_cs4(prow + 4 * tx, make_float4(v0, v1, v2, v3));
        } else {
            if (tx < 255) {
                stg_cs4(prow + s + 4 * tx, make_float4(v0, v1, v2, v3));
            } else {
                // tail cols s+1020 .. 1023  (4-s values; window idx <= 3)
                stg_cs(prow + s + 1020 + 0, v0);
                if (1 < 4 - s) stg_cs(prow + s + 1020 + 1, v1);
                if (2 < 4 - s) stg_cs(prow + s + 1020 + 2, v2);
            }
            if (tx == 0) {
                // head cols 0 .. s-1
                #pragma unroll
                for (int j = 0; j < s; j++)
                    stg_cs(prow + j, lsig_fast(s0 + s1w[j], l0 + lw[j]));
            }
        }
    }
}

// ---- kernel 2: fused probs + corres + right edge + bottom row ----
__global__ void __launch_bounds__(256) fused_kernel(float* __restrict__ probs,
                                                    float* __restrict__ corres,
                                                    int has_corres) {
    int b  = blockIdx.z;
    int m0 = blockIdx.y * TM;
    int n0 = blockIdx.x * TN;
    int tx = threadIdx.x;

    // address/tile setup (independent of rows outputs)
    size_t pbase = (size_t)b * (M + 1) * (N + 1);
    float*  prow0 = probs + pbase + (size_t)m0 * (N + 1) + n0;
    float4* crow  = (float4*)(corres + (size_t)b * M * N + (size_t)m0 * N + n0) + tx;
    const bool wc = (has_corres != 0);
    int nwin  = b * N + n0 + 4 * tx;
    int nwin2 = (tx == 255) ? nwin : (nwin + 4);   // clamp; dup entries unused at tx=255

    // wait for rows' g_s0 / g_s1b / logsig arrays
    cudaGridDependencySynchronize();

    // reset the fold counter for the next launch (rows is complete here)
    if (blockIdx.x == 0 && blockIdx.y == 0 && blockIdx.z == 0 && tx == 0)
        g_ctr = 0;

    __shared__ float sh_s0[TM];
    __shared__ float sh_ls0[TM];
    if (tx < TM) {
        int r = b * M + m0 + tx;
        sh_s0[tx]  = g_s0[r];
        sh_ls0[tx] = g_ls0[r];
    }

    float4 a0 = *(const float4*)(g_s1b + nwin);
    float4 a1 = *(const float4*)(g_s1b + nwin2);
    float4 l0v = *(const float4*)(g_ls1 + nwin);
    float4 l1v = *(const float4*)(g_ls1 + nwin2);
    float s1w[8] = {a0.x, a0.y, a0.z, a0.w, a1.x, a1.y, a1.z, a1.w};
    float lw[8]  = {l0v.x, l0v.y, l0v.z, l0v.w, l1v.x, l1v.y, l1v.z, l1v.w};
    __syncthreads();

    switch (b & 3) {   // m0 % 8 == 0, so shift base depends only on b
        case 0: tile_body<0>(prow0, crow, sh_s0, sh_ls0, s1w, lw, tx, wc); break;
        case 1: tile_body<1>(prow0, crow, sh_s0, sh_ls0, s1w, lw, tx, wc); break;
        case 2: tile_body<2>(prow0, crow, sh_s0, sh_ls0, s1w, lw, tx, wc); break;
        default: tile_body<3>(prow0, crow, sh_s0, sh_ls0, s1w, lw, tx, wc); break;
    }

    // fused right-edge column: probs[b, m0..m0+TM-1, N] = logsig(-z0)
    if (blockIdx.x == (N / TN - 1) && tx < TM) {
        stg_cs(probs + pbase + (size_t)(m0 + tx) * (N + 1) + N, g_lsn0[b * M + m0 + tx]);
    }

    // fused bottom row (+ corner): blocks in the last row stripe write row M
    if (blockIdx.y == (M / TM - 1)) {
        float* brow = probs + pbase + (size_t)M * (N + 1);
        #pragma unroll
        for (int j = 0; j < 4; j++) {
            int n = n0 + tx + j * 256;
            stg_cs(brow + n, g_lsn1[b * N + n]);
        }
        if (blockIdx.x == (N / TN - 1) && tx == 0) stg_cs(brow + N, 0.0f);
    }
}

extern "C" void kernel_launch(void* const* d_in, const int* in_sizes, int n_in,
                              void* d_out, int out_size) {
    const float* desc0 = (const float*)d_in[0];
    const float* desc1 = (const float*)d_in[1];
    const float* W0    = (const float*)d_in[2];
    const float* b0    = (const float*)d_in[3];
    const float* W1    = (const float*)d_in[4];
    const float* b1    = (const float*)d_in[5];
    const float* Wm    = (const float*)d_in[6];
    const float* bm    = (const float*)d_in[7];
    const float* Wc    = (const float*)d_in[8];
    const float* bc    = (const float*)d_in[9];

    float* out = (float*)d_out;
    long long probs_elems  = (long long)B * (M + 1) * (N + 1);
    long long corres_elems = (long long)B * M * N;
    int has_corres = ((long long)out_size >= probs_elems + corres_elems) ? 1 : 0;
    float* probs  = out;
    float* corres = out + probs_elems;

    // kernel 1: fold + rows (1D grid; fold producers are bids 0..15)
    rows_kernel<<<B * M * 2 / 8, 256>>>(desc0, desc1, W0, b0, W1, b1,
                                        Wm, bm, Wc, bc);

    // kernel 2: PDL secondary — gates on rows via cudaGridDependencySynchronize
    cudaLaunchAttribute attrs[1];
    attrs[0].id = cudaLaunchAttributeProgrammaticStreamSerialization;
    attrs[0].val.programmaticStreamSerializationAllowed = 1;
    cudaLaunchConfig_t cfg = {};
    cfg.gridDim  = dim3(N / TN, M / TM, B);
    cfg.blockDim = dim3(256, 1, 1);
    cfg.attrs = attrs;
    cfg.numAttrs = 1;
    cudaLaunchKernelEx(&cfg, fused_kernel, probs, corres, has_corres);
}

// round 16
// speedup vs baseline: 1.0625x; 1.0625x over previous
#include <cuda_runtime.h>

#define B 8
#define M 2048
#define N 2048
#define IN 256
#define TM 8
#define TN 1024
#define NCHUNK 8
#define DCHUNK 16   // 128 / NCHUNK

// ---- scratch (allocation-free: __device__ globals) ----
__device__ float g_vp[2][NCHUNK][IN];   // partial folds of W^T @ Wc half
__device__ float g_consts[2];
__device__ float g_s0[B * M];       // s0 + const0
__device__ float g_ls0[B * M];      // logsig(z0)
__device__ float g_lsn0[B * M];     // logsig(-z0)
__device__ float g_s1b[B * N];      // s1 + const1 (bc folded)
__device__ float g_ls1[B * N];      // logsig(z1)
__device__ float g_lsn1[B * N];     // logsig(-z1)

// Negated coefficients of deg-6 poly for ln(1+u), u in [0,1]
#define PC0 (-1.79e-6f)
#define PC1 (-0.99984773f)
#define PC2 ( 0.49737292f)
#define PC3 (-0.31574592f)
#define PC4 ( 0.19035072f)
#define PC5 (-0.08269517f)
#define PC6 ( 0.01741517f)
#define NEG_L2E (-1.4426950408889634f)

__device__ __forceinline__ float ex2_(float x) {
    float r; asm("ex2.approx.f32 %0, %1;" : "=f"(r) : "f"(x)); return r;
}

// streaming (evict-first) stores: output is written once, never re-read
__device__ __forceinline__ void stg_cs4(float* p, float4 v) {
    asm volatile("st.global.cs.v4.f32 [%0], {%1, %2, %3, %4};"
                 :: "l"(p), "f"(v.x), "f"(v.y), "f"(v.z), "f"(v.w) : "memory");
}
__device__ __forceinline__ void stg_cs(float* p, float v) {
    asm volatile("st.global.cs.f32 [%0], %1;" :: "l"(p), "f"(v) : "memory");
}
// L2-only vector load (bypass L1: keep load wavefronts off the store-contended L1)
__device__ __forceinline__ float4 ldg_cg4(const float* p) {
    float4 v;
    asm volatile("ld.global.cg.v4.f32 {%0, %1, %2, %3}, [%4];"
                 : "=f"(v.x), "=f"(v.y), "=f"(v.z), "=f"(v.w) : "l"(p));
    return v;
}
__device__ __forceinline__ float ldg_cg(const float* p) {
    float v;
    asm volatile("ld.global.cg.f32 %0, [%1];" : "=f"(v) : "l"(p));
    return v;
}

__device__ __forceinline__ float lsig(float x) {   // reference-accurate, tiny arrays only
    return fminf(x, 0.0f) - __logf(1.0f + __expf(-fabsf(x)));
}

// fast scalar log-sigmoid + q:  min(c,0) - log1p(exp(-|c|)) + q
__device__ __forceinline__ float lsig_fast(float c, float q) {
    float u = ex2_(fabsf(c) * NEG_L2E);          // exp(-|c|), 1 MUFU
    float p = fmaf(PC6, u, PC5);
    p = fmaf(p, u, PC4);
    p = fmaf(p, u, PC3);
    p = fmaf(p, u, PC2);
    p = fmaf(p, u, PC1);
    p = fmaf(p, u, PC0);                         // p = -log1p(u)
    return fminf(c, 0.0f) + p + q;
}

// ---- kernel 0: partial fold of projection weights through Wc ----
__global__ void prep_kernel(const float* __restrict__ W0, const float* __restrict__ b0,
                            const float* __restrict__ W1, const float* __restrict__ b1,
                            const float* __restrict__ Wc, const float* __restrict__ bc) {
    int i = threadIdx.x;             // 0..255 (output column)
    int chunk = blockIdx.x;
    int which = blockIdx.y;
    const float* W  = which ? W1 : W0;
    const float* wc = Wc + which * 128;

    float a = 0.f;
    int d0 = chunk * DCHUNK;
    #pragma unroll
    for (int dd = 0; dd < DCHUNK; dd++) {
        int d = d0 + dd;
        a += W[d * IN + i] * wc[d];
    }
    g_vp[which][chunk][i] = a;

    if (chunk == 0 && i < 32) {
        const float* bias = which ? b1 : b0;
        float c = 0.f;
        #pragma unroll
        for (int d = i; d < 128; d += 32) c += bias[d] * wc[d];
        #pragma unroll
        for (int o = 16; o; o >>= 1) c += __shfl_down_sync(0xffffffffu, c, o);
        if (i == 0) g_consts[which] = which ? (c + bc[0]) : c;
    }
}

// ---- kernel 1: per-row dot products; one warp per row ----
// PDL secondary: desc loads + az accumulation run BEFORE the grid-dependency
// sync (independent of prep); only the g_vp fold-reduce waits.
__global__ void rows_kernel(const float* __restrict__ d0, const float* __restrict__ d1,
                            const float* __restrict__ Wm, const float* __restrict__ bm) {
    int which = blockIdx.y;
    const float* desc = which ? d1 : d0;
    int warp = threadIdx.x >> 5, lane = threadIdx.x & 31;
    int row = blockIdx.x * 8 + warp;
    int k0 = lane, k1 = lane + 32;

    // independent of prep: fetch desc row + Wm, accumulate az
    const float4* dp = (const float4*)(desc + (size_t)row * IN);
    float4 a0 = dp[k0];
    float4 a1 = dp[k1];
    float4 wv0 = ((const float4*)Wm)[k0];
    float4 wv1 = ((const float4*)Wm)[k1];
    float bmv = bm[0];
    float az = a0.x * wv0.x + a0.y * wv0.y + a0.z * wv0.z + a0.w * wv0.w
             + a1.x * wv1.x + a1.y * wv1.y + a1.z * wv1.z + a1.w * wv1.w;

    // wait for prep's g_vp / g_consts
    cudaGridDependencySynchronize();

    __shared__ float sh_v[IN];
    {
        float a = 0.f;
        #pragma unroll
        for (int c = 0; c < NCHUNK; c++) a += g_vp[which][c][threadIdx.x];
        sh_v[threadIdx.x] = a;
    }
    __syncthreads();

    float4 vv0 = ((const float4*)sh_v)[k0];
    float4 vv1 = ((const float4*)sh_v)[k1];
    float as = a0.x * vv0.x + a0.y * vv0.y + a0.z * vv0.z + a0.w * vv0.w
             + a1.x * vv1.x + a1.y * vv1.y + a1.z * vv1.z + a1.w * vv1.w;

    #pragma unroll
    for (int o = 16; o; o >>= 1) {
        as += __shfl_down_sync(0xffffffffu, as, o);
        az += __shfl_down_sync(0xffffffffu, az, o);
    }
    if (lane == 0) {
        float z = az + bmv;
        if (which == 0) {
            g_s0[row]   = as + g_consts[0];
            g_ls0[row]  = lsig(z);
            g_lsn0[row] = lsig(-z);
        } else {
            g_s1b[row]  = as + g_consts[1];
            g_ls1[row]  = lsig(z);
            g_lsn1[row] = lsig(-z);
        }
    }
}

// ---- fused tile body, templated on SB = b & 3 ----
// probs row (b,m) starts at global offset ≡ (b+m) mod 4; per-row shift
// s = (-(b+r)) & 3 makes stores at col s+4t 16B-aligned. Thread t holds an
// 8-value s1/ls1 register window (cols 4t..4t+7); threads 0/255 mop up
// <=4 boundary scalars per row. All stores use evict-first (.cs) hints.
template<int SB>
__device__ __forceinline__ void tile_body(
    float* __restrict__ prow0, float4* __restrict__ crow,
    const float* sh_s0, const float* sh_ls0,
    const float* s1w, const float* lw, int tx, bool wc)
{
    #pragma unroll
    for (int r = 0; r < TM; r++) {
        const int s = (16 - SB - r) & 3;   // alignment shift: (b+r+s) % 4 == 0
        float s0 = sh_s0[r];
        float l0 = sh_ls0[r];

        if (wc) {
            stg_cs4((float*)crow,
                    make_float4(s0 + s1w[0], s0 + s1w[1], s0 + s1w[2], s0 + s1w[3]));
            crow += N / 4;
        }

        float v0 = lsig_fast(s0 + s1w[s + 0], l0 + lw[s + 0]);
        float v1 = lsig_fast(s0 + s1w[s + 1], l0 + lw[s + 1]);
        float v2 = lsig_fast(s0 + s1w[s + 2], l0 + lw[s + 2]);
        float v3 = lsig_fast(s0 + s1w[s + 3], l0 + lw[s + 3]);

        float* prow = prow0 + (size_t)r * (N + 1);
        if (s == 0) {
            stg_cs4(prow + 4 * tx, make_float4(v0, v1, v2, v3));
        } else {
            if (tx < 255) {
                stg_cs4(prow + s + 4 * tx, make_float4(v0, v1, v2, v3));
            } else {
                // tail cols s+1020 .. 1023  (4-s values; window idx <= 3)
                stg_cs(prow + s + 1020 + 0, v0);
                if (1 < 4 - s) stg_cs(prow + s + 1020 + 1, v1);
                if (2 < 4 - s) stg_cs(prow + s + 1020 + 2, v2);
            }
            if (tx == 0) {
                // head cols 0 .. s-1
                #pragma unroll
                for (int j = 0; j < s; j++)
                    stg_cs(prow + j, lsig_fast(s0 + s1w[j], l0 + lw[j]));
            }
        }
    }
}

// ---- kernel 2: fused probs + corres + right edge + bottom row ----
__global__ void __launch_bounds__(256) fused_kernel(float* __restrict__ probs,
                                                    float* __restrict__ corres,
                                                    int has_corres) {
    int b  = blockIdx.z;
    int m0 = blockIdx.y * TM;
    int n0 = blockIdx.x * TN;
    int tx = threadIdx.x;

    // address/tile setup (independent of rows outputs)
    size_t pbase = (size_t)b * (M + 1) * (N + 1);
    float*  prow0 = probs + pbase + (size_t)m0 * (N + 1) + n0;
    float4* crow  = (float4*)(corres + (size_t)b * M * N + (size_t)m0 * N + n0) + tx;
    const bool wc = (has_corres != 0);
    int nwin  = b * N + n0 + 4 * tx;
    int nwin2 = (tx == 255) ? nwin : (nwin + 4);   // clamp; dup entries unused at tx=255

    // wait for rows' g_s0 / g_s1b / logsig arrays
    cudaGridDependencySynchronize();

    __shared__ float sh_s0[TM];
    __shared__ float sh_ls0[TM];
    if (tx < TM) {
        int r = b * M + m0 + tx;
        sh_s0[tx]  = ldg_cg(&g_s0[r]);
        sh_ls0[tx] = ldg_cg(&g_ls0[r]);
    }

    // table loads via L2-only path: keep L1 free for the store stream
    float4 a0 = ldg_cg4(g_s1b + nwin);
    float4 a1 = ldg_cg4(g_s1b + nwin2);
    float4 l0v = ldg_cg4(g_ls1 + nwin);
    float4 l1v = ldg_cg4(g_ls1 + nwin2);
    float s1w[8] = {a0.x, a0.y, a0.z, a0.w, a1.x, a1.y, a1.z, a1.w};
    float lw[8]  = {l0v.x, l0v.y, l0v.z, l0v.w, l1v.x, l1v.y, l1v.z, l1v.w};
    __syncthreads();

    switch (b & 3) {   // m0 % 8 == 0, so shift base depends only on b
        case 0: tile_body<0>(prow0, crow, sh_s0, sh_ls0, s1w, lw, tx, wc); break;
        case 1: tile_body<1>(prow0, crow, sh_s0, sh_ls0, s1w, lw, tx, wc); break;
        case 2: tile_body<2>(prow0, crow, sh_s0, sh_ls0, s1w, lw, tx, wc); break;
        default: tile_body<3>(prow0, crow, sh_s0, sh_ls0, s1w, lw, tx, wc); break;
    }

    // fused right-edge column: probs[b, m0..m0+TM-1, N] = logsig(-z0)
    if (blockIdx.x == (N / TN - 1) && tx < TM) {
        stg_cs(probs + pbase + (size_t)(m0 + tx) * (N + 1) + N,
               ldg_cg(&g_lsn0[b * M + m0 + tx]));
    }

    // fused bottom row (+ corner): blocks in the last row stripe write row M
    if (blockIdx.y == (M / TM - 1)) {
        float* brow = probs + pbase + (size_t)M * (N + 1);
        #pragma unroll
        for (int j = 0; j < 4; j++) {
            int n = n0 + tx + j * 256;
            stg_cs(brow + n, ldg_cg(&g_lsn1[b * N + n]));
        }
        if (blockIdx.x == (N / TN - 1) && tx == 0) stg_cs(brow + N, 0.0f);
    }
}

extern "C" void kernel_launch(void* const* d_in, const int* in_sizes, int n_in,
                              void* d_out, int out_size) {
    const float* desc0 = (const float*)d_in[0];
    const float* desc1 = (const float*)d_in[1];
    const float* W0    = (const float*)d_in[2];
    const float* b0    = (const float*)d_in[3];
    const float* W1    = (const float*)d_in[4];
    const float* b1    = (const float*)d_in[5];
    const float* Wm    = (const float*)d_in[6];
    const float* bm    = (const float*)d_in[7];
    const float* Wc    = (const float*)d_in[8];
    const float* bc    = (const float*)d_in[9];

    float* out = (float*)d_out;
    long long probs_elems  = (long long)B * (M + 1) * (N + 1);
    long long corres_elems = (long long)B * M * N;
    int has_corres = ((long long)out_size >= probs_elems + corres_elems) ? 1 : 0;
    float* probs  = out;
    float* corres = out + probs_elems;

    // primary: normal launch
    prep_kernel<<<dim3(NCHUNK, 2), 256>>>(W0, b0, W1, b1, Wc, bc);

    // PDL: allow overlap with predecessor; kernels gate on
    // cudaGridDependencySynchronize() before consuming upstream data.
    cudaLaunchAttribute attrs[1];
    attrs[0].id = cudaLaunchAttributeProgrammaticStreamSerialization;
    attrs[0].val.programmaticStreamSerializationAllowed = 1;

    {
        cudaLaunchConfig_t cfg = {};
        cfg.gridDim  = dim3(B * M / 8, 2, 1);
        cfg.blockDim = dim3(256, 1, 1);
        cfg.attrs = attrs;
        cfg.numAttrs = 1;
        cudaLaunchKernelEx(&cfg, rows_kernel, desc0, desc1, Wm, bm);
    }
    {
        cudaLaunchConfig_t cfg = {};
        cfg.gridDim  = dim3(N / TN, M / TM, B);
        cfg.blockDim = dim3(256, 1, 1);
        cfg.attrs = attrs;
        cfg.numAttrs = 1;
        cudaLaunchKernelEx(&cfg, fused_kernel, probs, corres, has_corres);
    }
}